// round 1
// baseline (speedup 1.0000x reference)
#include <cuda_runtime.h>
#include <math.h>

#define N_ATOMS 50000
#define E_EDGES 1600000
#define H_DIM   128
#define B_GR    64
#define T_OUT   4
#define G_RBF   10
#define HH      (H_DIM*H_DIM)

// -------- scratch (device globals; no allocations allowed) --------
__device__ float g_d[E_EDGES];
__device__ float g_h [N_ATOMS*H_DIM];
__device__ float g_hx[N_ATOMS*H_DIM];   // lin1 output (gather source), later reused as tmp/h3
__device__ float g_agg[N_ATOMS*H_DIM];
__device__ float g_h2[N_ATOMS*64];
__device__ float g_pool[B_GR*H_DIM];

__device__ __forceinline__ float sspf(float x) {
    // softplus(x) - ln(2), numerically stable
    float sp = fmaxf(x, 0.0f) + log1pf(expf(-fabsf(x)));
    return sp - 0.69314718055994530942f;
}

// -------- edge distances --------
__global__ void dist_kernel(const int* __restrict__ ei, const float* __restrict__ pos) {
    int e = blockIdx.x * 256 + threadIdx.x;
    if (e < E_EDGES) {
        int s = ei[e], d = ei[E_EDGES + e];
        float dx = pos[s*3+0] - pos[d*3+0];
        float dy = pos[s*3+1] - pos[d*3+1];
        float dz = pos[s*3+2] - pos[d*3+2];
        g_d[e] = sqrtf(dx*dx + dy*dy + dz*dz);
    }
}

// -------- embedding gather --------
__global__ void embed_kernel(const int* __restrict__ z, const float* __restrict__ emb) {
    int idx = blockIdx.x * 256 + threadIdx.x;
    if (idx < N_ATOMS*H_DIM) {
        int n = idx >> 7;
        g_h[idx] = emb[z[n]*H_DIM + (idx & 127)];
    }
}

// -------- generic node GEMM: Cout[M,NN] = op(A[M,K] @ W[K,NN] + bias) (+resid) --------
template<int K, int NN, int TN, bool SSP, bool RESID>
__global__ void __launch_bounds__(256)
node_gemm(const float* __restrict__ A, const float* __restrict__ W,
          const float* __restrict__ bias, const float* __restrict__ resid,
          float* __restrict__ Cout, int M)
{
    __shared__ float sA[128][16];
    __shared__ float sW[16][NN];
    const int tid = threadIdx.x, ty = tid >> 4, tx = tid & 15;
    const int row0 = blockIdx.x * 128;

    float acc[8][TN];
#pragma unroll
    for (int i = 0; i < 8; i++)
#pragma unroll
        for (int j = 0; j < TN; j++) acc[i][j] = 0.0f;

    for (int kt = 0; kt < K; kt += 16) {
        for (int idx = tid; idx < 128*16; idx += 256) {
            int r = idx >> 4, kk = idx & 15;
            int gr = row0 + r;
            sA[r][kk] = (gr < M) ? A[gr*K + kt + kk] : 0.0f;
        }
        for (int idx = tid; idx < 16*NN; idx += 256) {
            int kk = idx / NN, c = idx - kk*NN;
            sW[kk][c] = W[(kt + kk)*NN + c];
        }
        __syncthreads();
#pragma unroll
        for (int kk = 0; kk < 16; kk++) {
            float a[8];
#pragma unroll
            for (int i = 0; i < 8; i++) a[i] = sA[ty*8 + i][kk];
            float b[TN];
#pragma unroll
            for (int j = 0; j < TN; j += 4) {
                float4 v = *reinterpret_cast<const float4*>(&sW[kk][tx*TN + j]);
                b[j] = v.x; b[j+1] = v.y; b[j+2] = v.z; b[j+3] = v.w;
            }
#pragma unroll
            for (int i = 0; i < 8; i++)
#pragma unroll
                for (int j = 0; j < TN; j++) acc[i][j] = fmaf(a[i], b[j], acc[i][j]);
        }
        __syncthreads();
    }

#pragma unroll
    for (int i = 0; i < 8; i++) {
        int gr = row0 + ty*8 + i;
        if (gr < M) {
#pragma unroll
            for (int j = 0; j < TN; j++) {
                int c = tx*TN + j;
                float v = acc[i][j];
                if (bias) v += bias[c];
                if (SSP)  v = sspf(v);
                if (RESID) v += resid[gr*NN + c];
                Cout[gr*NN + c] = v;
            }
        }
    }
}

// -------- fused edge kernel --------
// per tile of 128 edges: rbf -> t1 = ssp(rbf@W1+b1) (smem) -> Wf = t1@W2+b2 (block SGEMM)
// -> *= C(d) -> *= hx[src] -> atomicAdd into agg[dst]
struct EdgeSmem {
    float t1[128][128];   // 64 KB
    float Bt[16][128];    // 8 KB (W2 k-slab)
    float w1[G_RBF][128]; // 5 KB
    float rbf[128][G_RBF];
    float b1s[128];
    float b2s[128];
    float Ce[128];
    int   src[128];
    int   dst[128];
};

__global__ void __launch_bounds__(256, 2)
edge_kernel(const int* __restrict__ ei,
            const float* __restrict__ w1g, const float* __restrict__ b1g,
            const float* __restrict__ w2g, const float* __restrict__ b2g)
{
    extern __shared__ char smem_raw[];
    EdgeSmem& s = *reinterpret_cast<EdgeSmem*>(smem_raw);
    const int tid = threadIdx.x;
    const int base = blockIdx.x * 128;

    for (int idx = tid; idx < G_RBF*128; idx += 256) s.w1[idx >> 7][idx & 127] = w1g[idx];
    if (tid < 128) {
        s.b1s[tid] = b1g[tid];
        s.b2s[tid] = b2g[tid];
        int e = base + tid;
        s.src[tid] = ei[e];
        s.dst[tid] = ei[E_EDGES + e];
        float dd = g_d[e];
        s.Ce[tid] = 0.5f * (cospif(dd * 0.1f) + 1.0f);
        const float step  = 10.0f / 9.0f;
        const float coeff = -0.405f;   // -0.5 / (10/9)^2
#pragma unroll
        for (int g = 0; g < G_RBF; g++) {
            float t = dd - step * (float)g;
            s.rbf[tid][g] = expf(coeff * t * t);
        }
    }
    __syncthreads();

    // t1 = ssp(rbf @ W1 + b1)  [128 edges x 128]
    for (int idx = tid; idx < 128*128; idx += 256) {
        int e = idx >> 7, hh = idx & 127;
        float v = s.b1s[hh];
#pragma unroll
        for (int g = 0; g < G_RBF; g++) v = fmaf(s.rbf[e][g], s.w1[g][hh], v);
        s.t1[e][hh] = sspf(v);
    }
    __syncthreads();

    // block SGEMM: Wf = t1 @ W2   (128x128x128), thread computes 8x8
    const int ty = tid >> 4, tx = tid & 15;
    const int r0 = ty * 8, c0 = tx * 8;
    float acc[8][8];
#pragma unroll
    for (int i = 0; i < 8; i++)
#pragma unroll
        for (int j = 0; j < 8; j++) acc[i][j] = 0.0f;

    for (int kt = 0; kt < 128; kt += 16) {
        for (int idx = tid; idx < 16*128; idx += 256) {
            int kk = idx >> 7, c = idx & 127;
            s.Bt[kk][c] = w2g[(kt + kk)*H_DIM + c];
        }
        __syncthreads();
#pragma unroll
        for (int kk = 0; kk < 16; kk++) {
            float a[8];
#pragma unroll
            for (int i = 0; i < 8; i++) a[i] = s.t1[r0 + i][kt + kk];
            float4 bv0 = *reinterpret_cast<const float4*>(&s.Bt[kk][c0]);
            float4 bv1 = *reinterpret_cast<const float4*>(&s.Bt[kk][c0 + 4]);
            float b[8] = {bv0.x, bv0.y, bv0.z, bv0.w, bv1.x, bv1.y, bv1.z, bv1.w};
#pragma unroll
            for (int i = 0; i < 8; i++)
#pragma unroll
                for (int j = 0; j < 8; j++) acc[i][j] = fmaf(a[i], b[j], acc[i][j]);
        }
        __syncthreads();
    }

    // epilogue: (+b2)*C * hx[src]  -> atomic scatter to agg[dst]
#pragma unroll
    for (int i = 0; i < 8; i++) {
        int e = r0 + i;
        float ce = s.Ce[e];
        int sr = s.src[e], ds = s.dst[e];
        const float4* hxp = reinterpret_cast<const float4*>(&g_hx[sr*H_DIM + c0]);
        float4 x0 = hxp[0], x1 = hxp[1];
        float xv[8] = {x0.x, x0.y, x0.z, x0.w, x1.x, x1.y, x1.z, x1.w};
        float* ap = &g_agg[ds*H_DIM + c0];
#pragma unroll
        for (int j = 0; j < 8; j++) {
            float wv = (acc[i][j] + s.b2s[c0 + j]) * ce;
            atomicAdd(ap + j, wv * xv[j]);
        }
    }
}

// -------- readout pooling + prediction --------
__global__ void pool_kernel(const int* __restrict__ batch, const float* __restrict__ h3) {
    int idx = blockIdx.x * 256 + threadIdx.x;
    if (idx < N_ATOMS*H_DIM) {
        int n = idx >> 7;
        atomicAdd(&g_pool[batch[n]*H_DIM + (idx & 127)], h3[idx]);
    }
}

__global__ void pred_kernel(const float* __restrict__ pw, const float* __restrict__ pb,
                            float* __restrict__ out) {
    int t = threadIdx.x;
    if (t < B_GR*T_OUT) {
        int b = t >> 2, c = t & 3;
        float acc = pb[c];
        for (int h = 0; h < H_DIM; h++)
            acc = fmaf(g_pool[b*H_DIM + h], pw[h*T_OUT + c], acc);
        out[t] = acc;
    }
}

extern "C" void kernel_launch(void* const* d_in, const int* in_sizes, int n_in,
                              void* d_out, int out_size)
{
    const int*   z      = (const int*)  d_in[0];
    const float* pos    = (const float*)d_in[1];
    const int*   batch  = (const int*)  d_in[2];
    const int*   ei     = (const int*)  d_in[3];
    const float* emb    = (const float*)d_in[4];
    const float* mlp_w1 = (const float*)d_in[5];
    const float* mlp_b1 = (const float*)d_in[6];
    const float* mlp_w2 = (const float*)d_in[7];
    const float* mlp_b2 = (const float*)d_in[8];
    const float* lin1_w = (const float*)d_in[9];
    const float* lin2_w = (const float*)d_in[10];
    const float* lin2_b = (const float*)d_in[11];
    const float* lin_w  = (const float*)d_in[12];
    const float* lin_b  = (const float*)d_in[13];
    const float* out1_w = (const float*)d_in[14];
    const float* out1_b = (const float*)d_in[15];
    const float* out2_w = (const float*)d_in[16];
    const float* out2_b = (const float*)d_in[17];
    const float* pred_w = (const float*)d_in[18];
    const float* pred_b = (const float*)d_in[19];
    float* out = (float*)d_out;

    void *h_p, *hx_p, *agg_p, *h2_p, *pool_p;
    cudaGetSymbolAddress(&h_p,    g_h);
    cudaGetSymbolAddress(&hx_p,   g_hx);
    cudaGetSymbolAddress(&agg_p,  g_agg);
    cudaGetSymbolAddress(&h2_p,   g_h2);
    cudaGetSymbolAddress(&pool_p, g_pool);
    float* hF   = (float*)h_p;
    float* hxF  = (float*)hx_p;
    float* aggF = (float*)agg_p;
    float* h2F  = (float*)h2_p;

    const int smem = (int)sizeof(EdgeSmem);
    cudaFuncSetAttribute(edge_kernel, cudaFuncAttributeMaxDynamicSharedMemorySize, smem);

    dist_kernel <<<(E_EDGES + 255)/256, 256>>>(ei, pos);
    embed_kernel<<<(N_ATOMS*H_DIM + 255)/256, 256>>>(z, emb);

    const int NB = (N_ATOMS + 127) / 128;   // 391
    for (int i = 0; i < 2; i++) {
        // hx = h @ lin1_w (no bias)
        node_gemm<128,128,8,false,false><<<NB,256>>>(hF, lin1_w + i*HH, nullptr, nullptr, hxF, N_ATOMS);
        // agg = 0
        cudaMemsetAsync(agg_p, 0, (size_t)N_ATOMS*H_DIM*sizeof(float));
        // fused edge pass
        edge_kernel<<<E_EDGES/128, 256, smem>>>(ei, mlp_w1 + i*G_RBF*H_DIM, mlp_b1 + i*H_DIM,
                                                mlp_w2 + i*HH, mlp_b2 + i*H_DIM);
        // tmp = ssp(agg @ lin2_w + lin2_b)   (tmp reuses hx buffer)
        node_gemm<128,128,8,true,false><<<NB,256>>>(aggF, lin2_w + i*HH, lin2_b + i*H_DIM, nullptr, hxF, N_ATOMS);
        // h = h + (tmp @ lin_w + lin_b)
        node_gemm<128,128,8,false,true><<<NB,256>>>(hxF, lin_w + i*HH, lin_b + i*H_DIM, hF, hF, N_ATOMS);
    }

    // h2 = ssp(h @ out1_w + out1_b)   [N,64]
    node_gemm<128,64,4,true,false><<<NB,256>>>(hF, out1_w, out1_b, nullptr, h2F, N_ATOMS);
    // h3 = h2 @ out2_w + out2_b       [N,128]  (reuse hx buffer)
    node_gemm<64,128,8,false,false><<<NB,256>>>(h2F, out2_w, out2_b, nullptr, hxF, N_ATOMS);

    cudaMemsetAsync(pool_p, 0, (size_t)B_GR*H_DIM*sizeof(float));
    pool_kernel<<<(N_ATOMS*H_DIM + 255)/256, 256>>>(batch, hxF);
    pred_kernel<<<1, 256>>>(pred_w, pred_b, out);
}

// round 5
// speedup vs baseline: 5.0442x; 5.0442x over previous
#include <cuda_runtime.h>
#include <math.h>

#define N_ATOMS 50000
#define E_EDGES 1600000
#define H_DIM   128
#define B_GR    64
#define T_OUT   4
#define G_RBF   10
#define HH      (H_DIM*H_DIM)
#define TBL     1024
#define DMAX    10.0f

// -------- scratch (device globals; no allocations allowed) --------
__device__ float g_h  [N_ATOMS*H_DIM];
__device__ float g_hx [N_ATOMS*H_DIM];   // lin1 output (gather source), later reused as tmp
__device__ float g_agg[N_ATOMS*H_DIM];
__device__ float g_h2 [N_ATOMS*64];
__device__ float g_tbl[2*TBL*H_DIM];     // per-interaction filter tables W(d)
__device__ float g_pool2[B_GR*64];
__device__ float g_cnt[B_GR];

__device__ __forceinline__ float sspf(float x) {
    float sp = fmaxf(x, 0.0f) + log1pf(expf(-fabsf(x)));
    return sp - 0.69314718055994530942f;
}

// -------- embedding gather --------
__global__ void embed_kernel(const int* __restrict__ z, const float* __restrict__ emb) {
    int idx = blockIdx.x * 256 + threadIdx.x;
    if (idx < N_ATOMS*H_DIM) {
        int n = idx >> 7;
        g_h[idx] = emb[z[n]*H_DIM + (idx & 127)];
    }
}

// -------- filter table build: tbl[it][k][h] = W_h(d_k) --------
// W(d) = (ssp(rbf(d)@W1 + b1) @ W2 + b2) * C(d)
__global__ void build_table(const float* __restrict__ w1, const float* __restrict__ b1,
                            const float* __restrict__ w2, const float* __restrict__ b2)
{
    __shared__ float t1[H_DIM];
    const int k = blockIdx.x, it = blockIdx.y, h = threadIdx.x;
    const float d = (float)k * (DMAX / (float)(TBL - 1));
    const float step  = 10.0f / 9.0f;
    const float coeff = -0.405f;   // -0.5/(10/9)^2 exactly

    float v = b1[it*H_DIM + h];
    const float* w1p = w1 + it*G_RBF*H_DIM;
#pragma unroll
    for (int g = 0; g < G_RBF; g++) {
        float t = d - step * (float)g;
        v = fmaf(expf(coeff * t * t), w1p[g*H_DIM + h], v);
    }
    t1[h] = sspf(v);
    __syncthreads();

    const float* w2p = w2 + it*HH;
    float acc = b2[it*H_DIM + h];
#pragma unroll 8
    for (int kk = 0; kk < H_DIM; kk++)
        acc = fmaf(t1[kk], w2p[kk*H_DIM + h], acc);

    float C = 0.5f * (cospif(d * 0.1f) + 1.0f);
    g_tbl[(it*TBL + k)*H_DIM + h] = acc * C;
}

// -------- edge pass: one warp per edge --------
// w = lerp(tbl[d]); agg[dst] += w * hx[src]  (vector red)
#define EPW 2
__global__ void __launch_bounds__(256)
edge_pass(const int* __restrict__ ei, const float* __restrict__ pos,
          const float* __restrict__ tbl)
{
    const int gw   = (blockIdx.x * 256 + threadIdx.x) >> 5;
    const int lane = threadIdx.x & 31;
    const int e0 = gw * EPW;
    const float scale = (float)(TBL - 1) / DMAX;

#pragma unroll
    for (int j = 0; j < EPW; j++) {
        int e = e0 + j;
        if (e >= E_EDGES) return;
        int s  = __ldg(&ei[e]);
        int dn = __ldg(&ei[E_EDGES + e]);
        float dx = __ldg(&pos[s*3+0]) - __ldg(&pos[dn*3+0]);
        float dy = __ldg(&pos[s*3+1]) - __ldg(&pos[dn*3+1]);
        float dz = __ldg(&pos[s*3+2]) - __ldg(&pos[dn*3+2]);
        float d = sqrtf(dx*dx + dy*dy + dz*dz);

        float tt = d * scale;
        int i0 = (int)tt;
        i0 = min(i0, TBL - 2);
        float f = tt - (float)i0;

        const float4* r0 = reinterpret_cast<const float4*>(tbl + i0*H_DIM);
        float4 a = __ldg(&r0[lane]);        // row i0
        float4 b = __ldg(&r0[lane + 32]);   // row i0+1 (stride 128 floats = 32 float4)
        float4 x = __ldg(reinterpret_cast<const float4*>(g_hx + (size_t)s*H_DIM) + lane);

        float4 w;
        w.x = fmaf(f, b.x - a.x, a.x) * x.x;
        w.y = fmaf(f, b.y - a.y, a.y) * x.y;
        w.z = fmaf(f, b.z - a.z, a.z) * x.z;
        w.w = fmaf(f, b.w - a.w, a.w) * x.w;

        float* ap = g_agg + (size_t)dn*H_DIM + lane*4;
        asm volatile("red.global.add.v4.f32 [%0], {%1,%2,%3,%4};"
                     :: "l"(ap), "f"(w.x), "f"(w.y), "f"(w.z), "f"(w.w) : "memory");
    }
}

// -------- generic node GEMM: Cout[M,NN] = op(A[M,K] @ W[K,NN] + bias) (+resid) --------
template<int K, int NN, int TN, bool SSP, bool RESID>
__global__ void __launch_bounds__(256)
node_gemm(const float* __restrict__ A, const float* __restrict__ W,
          const float* __restrict__ bias, const float* __restrict__ resid,
          float* __restrict__ Cout, int M)
{
    __shared__ float sA[128][16];
    __shared__ float sW[16][NN];
    const int tid = threadIdx.x, ty = tid >> 4, tx = tid & 15;
    const int row0 = blockIdx.x * 128;

    float acc[8][TN];
#pragma unroll
    for (int i = 0; i < 8; i++)
#pragma unroll
        for (int j = 0; j < TN; j++) acc[i][j] = 0.0f;

    for (int kt = 0; kt < K; kt += 16) {
        for (int idx = tid; idx < 128*16; idx += 256) {
            int r = idx >> 4, kk = idx & 15;
            int gr = row0 + r;
            sA[r][kk] = (gr < M) ? A[gr*K + kt + kk] : 0.0f;
        }
        for (int idx = tid; idx < 16*NN; idx += 256) {
            int kk = idx / NN, c = idx - kk*NN;
            sW[kk][c] = W[(kt + kk)*NN + c];
        }
        __syncthreads();
#pragma unroll
        for (int kk = 0; kk < 16; kk++) {
            float a[8];
#pragma unroll
            for (int i = 0; i < 8; i++) a[i] = sA[ty*8 + i][kk];
            float b[TN];
#pragma unroll
            for (int j = 0; j < TN; j += 4) {
                float4 v = *reinterpret_cast<const float4*>(&sW[kk][tx*TN + j]);
                b[j] = v.x; b[j+1] = v.y; b[j+2] = v.z; b[j+3] = v.w;
            }
#pragma unroll
            for (int i = 0; i < 8; i++)
#pragma unroll
                for (int j = 0; j < TN; j++) acc[i][j] = fmaf(a[i], b[j], acc[i][j]);
        }
        __syncthreads();
    }

#pragma unroll
    for (int i = 0; i < 8; i++) {
        int gr = row0 + ty*8 + i;
        if (gr < M) {
#pragma unroll
            for (int j = 0; j < TN; j++) {
                int c = tx*TN + j;
                float v = acc[i][j];
                if (bias) v += bias[c];
                if (SSP)  v = sspf(v);
                if (RESID) v += resid[gr*NN + c];
                Cout[gr*NN + c] = v;
            }
        }
    }
}

// -------- readout: pool h2 [N,64] per graph + atom counts --------
__global__ void pool2_kernel(const int* __restrict__ batch) {
    int idx = blockIdx.x * 256 + threadIdx.x;
    if (idx < N_ATOMS*64) {
        int n = idx >> 6, c = idx & 63;
        int b = batch[n];
        atomicAdd(&g_pool2[b*64 + c], g_h2[idx]);
        if (c == 0) atomicAdd(&g_cnt[b], 1.0f);
    }
}

// -------- final: out = P2 @ (out2_w@pred_w) + cnt*(out2_b@pred_w) + pred_b --------
__global__ void final_kernel(const float* __restrict__ out2w, const float* __restrict__ out2b,
                             const float* __restrict__ predw, const float* __restrict__ predb,
                             float* __restrict__ out)
{
    __shared__ float M[64*T_OUT];
    __shared__ float obp[T_OUT];
    int t = threadIdx.x;   // 256 threads
    {
        int c = t >> 2, j = t & 3;
        float acc = 0.0f;
        for (int h = 0; h < H_DIM; h++)
            acc = fmaf(out2w[c*H_DIM + h], predw[h*T_OUT + j], acc);
        M[c*T_OUT + j] = acc;
    }
    if (t < T_OUT) {
        float acc = 0.0f;
        for (int h = 0; h < H_DIM; h++)
            acc = fmaf(out2b[h], predw[h*T_OUT + t], acc);
        obp[t] = acc;
    }
    __syncthreads();
    int b = t >> 2, j = t & 3;
    float acc = predb[j] + g_cnt[b] * obp[j];
    for (int c = 0; c < 64; c++)
        acc = fmaf(g_pool2[b*64 + c], M[c*T_OUT + j], acc);
    out[b*T_OUT + j] = acc;
}

extern "C" void kernel_launch(void* const* d_in, const int* in_sizes, int n_in,
                              void* d_out, int out_size)
{
    const int*   z      = (const int*)  d_in[0];
    const float* pos    = (const float*)d_in[1];
    const int*   batch  = (const int*)  d_in[2];
    const int*   ei     = (const int*)  d_in[3];
    const float* emb    = (const float*)d_in[4];
    const float* mlp_w1 = (const float*)d_in[5];
    const float* mlp_b1 = (const float*)d_in[6];
    const float* mlp_w2 = (const float*)d_in[7];
    const float* mlp_b2 = (const float*)d_in[8];
    const float* lin1_w = (const float*)d_in[9];
    const float* lin2_w = (const float*)d_in[10];
    const float* lin2_b = (const float*)d_in[11];
    const float* lin_w  = (const float*)d_in[12];
    const float* lin_b  = (const float*)d_in[13];
    const float* out1_w = (const float*)d_in[14];
    const float* out1_b = (const float*)d_in[15];
    const float* out2_w = (const float*)d_in[16];
    const float* out2_b = (const float*)d_in[17];
    const float* pred_w = (const float*)d_in[18];
    const float* pred_b = (const float*)d_in[19];
    float* out = (float*)d_out;

    void *h_p, *hx_p, *agg_p, *h2_p, *tbl_p, *pool_p, *cnt_p;
    cudaGetSymbolAddress(&h_p,    g_h);
    cudaGetSymbolAddress(&hx_p,   g_hx);
    cudaGetSymbolAddress(&agg_p,  g_agg);
    cudaGetSymbolAddress(&h2_p,   g_h2);
    cudaGetSymbolAddress(&tbl_p,  g_tbl);
    cudaGetSymbolAddress(&pool_p, g_pool2);
    cudaGetSymbolAddress(&cnt_p,  g_cnt);
    float* hF   = (float*)h_p;
    float* hxF  = (float*)hx_p;
    float* aggF = (float*)agg_p;
    float* h2F  = (float*)h2_p;
    float* tblF = (float*)tbl_p;

    embed_kernel<<<(N_ATOMS*H_DIM + 255)/256, 256>>>(z, emb);
    build_table<<<dim3(TBL, 2), H_DIM>>>(mlp_w1, mlp_b1, mlp_w2, mlp_b2);

    const int NB = (N_ATOMS + 127) / 128;
    const int EB = (E_EDGES / EPW + 7) / 8;   // 8 warps/block, EPW edges/warp
    for (int i = 0; i < 2; i++) {
        node_gemm<128,128,8,false,false><<<NB,256>>>(hF, lin1_w + i*HH, nullptr, nullptr, hxF, N_ATOMS);
        cudaMemsetAsync(agg_p, 0, (size_t)N_ATOMS*H_DIM*sizeof(float));
        edge_pass<<<EB, 256>>>(ei, pos, tblF + i*TBL*H_DIM);
        node_gemm<128,128,8,true,false><<<NB,256>>>(aggF, lin2_w + i*HH, lin2_b + i*H_DIM, nullptr, hxF, N_ATOMS);
        node_gemm<128,128,8,false,true><<<NB,256>>>(hxF, lin_w + i*HH, lin_b + i*H_DIM, hF, hF, N_ATOMS);
    }

    // h2 = ssp(h @ out1_w + out1_b)  [N,64]
    node_gemm<128,64,4,true,false><<<NB,256>>>(hF, out1_w, out1_b, nullptr, h2F, N_ATOMS);

    cudaMemsetAsync(pool_p, 0, (size_t)B_GR*64*sizeof(float));
    cudaMemsetAsync(cnt_p,  0, (size_t)B_GR*sizeof(float));
    pool2_kernel<<<(N_ATOMS*64 + 255)/256, 256>>>(batch);
    final_kernel<<<1, 256>>>(out2_w, out2_b, pred_w, pred_b, out);
}

// round 10
// speedup vs baseline: 6.7307x; 1.3343x over previous
#include <cuda_runtime.h>
#include <math.h>
#include <stdint.h>

#define N_ATOMS 50000
#define E_EDGES 1600000
#define H_DIM   128
#define B_GR    64
#define T_OUT   4
#define G_RBF   10
#define HH      (H_DIM*H_DIM)
#define TBL     1024
#define DMAX    10.0f

// -------- scratch (device globals; no allocations allowed) --------
__device__ float g_h  [N_ATOMS*H_DIM];
__device__ float g_hx [N_ATOMS*H_DIM];
__device__ float g_agg[N_ATOMS*H_DIM];
__device__ float g_h2 [N_ATOMS*64];
__device__ float g_tbl[2*TBL*H_DIM];
__device__ float g_pool2[B_GR*64];
__device__ float g_cnt[B_GR];

__device__ __forceinline__ float sspf(float x) {
    float sp = fmaxf(x, 0.0f) + log1pf(expf(-fabsf(x)));
    return sp - 0.69314718055994530942f;
}

__device__ __forceinline__ uint32_t tf32_of(float x) {
    uint32_t r;
    asm("cvt.rna.tf32.f32 %0, %1;" : "=r"(r) : "f"(x));
    return r;
}

__device__ __forceinline__ void mma_tf32(float* c, uint32_t a0, uint32_t a1,
                                         uint32_t a2, uint32_t a3,
                                         uint32_t b0, uint32_t b1) {
    asm volatile(
        "mma.sync.aligned.m16n8k8.row.col.f32.tf32.tf32.f32 "
        "{%0,%1,%2,%3}, {%4,%5,%6,%7}, {%8,%9}, {%0,%1,%2,%3};"
        : "+f"(c[0]), "+f"(c[1]), "+f"(c[2]), "+f"(c[3])
        : "r"(a0), "r"(a1), "r"(a2), "r"(a3), "r"(b0), "r"(b1));
}

// -------- embedding gather --------
__global__ void embed_kernel(const int* __restrict__ z, const float* __restrict__ emb) {
    int idx = blockIdx.x * 256 + threadIdx.x;
    if (idx < N_ATOMS*H_DIM) {
        int n = idx >> 7;
        g_h[idx] = emb[z[n]*H_DIM + (idx & 127)];
    }
}

// -------- filter table build --------
__global__ void build_table(const float* __restrict__ w1, const float* __restrict__ b1,
                            const float* __restrict__ w2, const float* __restrict__ b2)
{
    __shared__ float t1[H_DIM];
    const int k = blockIdx.x, it = blockIdx.y, h = threadIdx.x;
    const float d = (float)k * (DMAX / (float)(TBL - 1));
    const float step  = 10.0f / 9.0f;
    const float coeff = -0.405f;

    float v = b1[it*H_DIM + h];
    const float* w1p = w1 + it*G_RBF*H_DIM;
#pragma unroll
    for (int g = 0; g < G_RBF; g++) {
        float t = d - step * (float)g;
        v = fmaf(expf(coeff * t * t), w1p[g*H_DIM + h], v);
    }
    t1[h] = sspf(v);
    __syncthreads();

    const float* w2p = w2 + it*HH;
    float acc = b2[it*H_DIM + h];
#pragma unroll 8
    for (int kk = 0; kk < H_DIM; kk++)
        acc = fmaf(t1[kk], w2p[kk*H_DIM + h], acc);

    float C = 0.5f * (cospif(d * 0.1f) + 1.0f);
    g_tbl[(it*TBL + k)*H_DIM + h] = acc * C;
}

// -------- edge pass: one warp per edge --------
#define EPW 2
__global__ void __launch_bounds__(256)
edge_pass(const int* __restrict__ ei, const float* __restrict__ pos,
          const float* __restrict__ tbl)
{
    const int gw   = (blockIdx.x * 256 + threadIdx.x) >> 5;
    const int lane = threadIdx.x & 31;
    const int e0 = gw * EPW;
    const float scale = (float)(TBL - 1) / DMAX;

#pragma unroll
    for (int j = 0; j < EPW; j++) {
        int e = e0 + j;
        if (e >= E_EDGES) return;
        int s  = __ldg(&ei[e]);
        int dn = __ldg(&ei[E_EDGES + e]);
        float dx = __ldg(&pos[s*3+0]) - __ldg(&pos[dn*3+0]);
        float dy = __ldg(&pos[s*3+1]) - __ldg(&pos[dn*3+1]);
        float dz = __ldg(&pos[s*3+2]) - __ldg(&pos[dn*3+2]);
        float d = sqrtf(dx*dx + dy*dy + dz*dz);

        float tt = d * scale;
        int i0 = (int)tt;
        i0 = min(i0, TBL - 2);
        float f = tt - (float)i0;

        const float4* r0 = reinterpret_cast<const float4*>(tbl + i0*H_DIM);
        float4 a = __ldg(&r0[lane]);
        float4 b = __ldg(&r0[lane + 32]);
        float4 x = __ldg(reinterpret_cast<const float4*>(g_hx + (size_t)s*H_DIM) + lane);

        float4 w;
        w.x = fmaf(f, b.x - a.x, a.x) * x.x;
        w.y = fmaf(f, b.y - a.y, a.y) * x.y;
        w.z = fmaf(f, b.z - a.z, a.z) * x.z;
        w.w = fmaf(f, b.w - a.w, a.w) * x.w;

        float* ap = g_agg + (size_t)dn*H_DIM + lane*4;
        asm volatile("red.global.add.v4.f32 [%0], {%1,%2,%3,%4};"
                     :: "l"(ap), "f"(w.x), "f"(w.y), "f"(w.z), "f"(w.w) : "memory");
    }
}

// -------- tensor-core node GEMM (tf32 HMMA) --------
// C[M,NN] = op(A[M,128] @ W[128,NN] + bias) (+resid)
// Block: 256 thr = 8 warps; each warp computes 16 rows x NN cols.
// W staged in smem (tf32-rounded, padded stride NN+8 -> conflict-free).
// A fragments loaded directly from global (each element read once per warp).
template<int NN, bool SSP_, bool RESID>
__global__ void __launch_bounds__(256)
node_gemm_tc(const float* __restrict__ A, const float* __restrict__ W,
             const float* __restrict__ bias, const float* __restrict__ resid,
             float* __restrict__ Cout, int M)
{
    constexpr int S  = NN + 8;
    constexpr int NT = NN / 8;
    extern __shared__ float sW[];   // [128][S]

    const int tid = threadIdx.x;
    // stage + tf32-round W
    for (int idx = tid; idx < 128*NN; idx += 256) {
        int k = idx / NN, n = idx - k*NN;
        sW[k*S + n] = __uint_as_float(tf32_of(W[idx]));
    }
    __syncthreads();

    const int warp = tid >> 5, lane = tid & 31;
    const int row0 = blockIdx.x * 128 + warp * 16;
    const int g  = lane >> 2;     // 0..7
    const int qc = lane & 3;      // 0..3
    const int rA0 = min(row0 + g,     M - 1);
    const int rA1 = min(row0 + 8 + g, M - 1);
    const float* A0 = A + (size_t)rA0 * 128 + qc;
    const float* A1 = A + (size_t)rA1 * 128 + qc;

    float acc[NT][4];
#pragma unroll
    for (int t = 0; t < NT; t++)
#pragma unroll
        for (int i = 0; i < 4; i++) acc[t][i] = 0.0f;

#pragma unroll
    for (int k0 = 0; k0 < 128; k0 += 8) {
        uint32_t a0 = tf32_of(__ldg(A0 + k0));
        uint32_t a2 = tf32_of(__ldg(A0 + k0 + 4));
        uint32_t a1 = tf32_of(__ldg(A1 + k0));
        uint32_t a3 = tf32_of(__ldg(A1 + k0 + 4));
        const float* bp0 = sW + (k0 + qc) * S + g;
        const float* bp1 = bp0 + 4 * S;
#pragma unroll
        for (int t = 0; t < NT; t++) {
            uint32_t b0 = __float_as_uint(bp0[t*8]);
            uint32_t b1 = __float_as_uint(bp1[t*8]);
            mma_tf32(acc[t], a0, a1, a2, a3, b0, b1);
        }
    }

    // epilogue
    const int r0 = row0 + g;
    const int r1 = r0 + 8;
#pragma unroll
    for (int t = 0; t < NT; t++) {
        int nc = t*8 + 2*qc;
        float bias0 = 0.f, bias1 = 0.f;
        if (bias) { bias0 = bias[nc]; bias1 = bias[nc+1]; }
        if (r0 < M) {
            float v0 = acc[t][0] + bias0;
            float v1 = acc[t][1] + bias1;
            if (SSP_) { v0 = sspf(v0); v1 = sspf(v1); }
            if (RESID) { v0 += resid[(size_t)r0*NN + nc]; v1 += resid[(size_t)r0*NN + nc + 1]; }
            Cout[(size_t)r0*NN + nc]     = v0;
            Cout[(size_t)r0*NN + nc + 1] = v1;
        }
        if (r1 < M) {
            float v2 = acc[t][2] + bias0;
            float v3 = acc[t][3] + bias1;
            if (SSP_) { v2 = sspf(v2); v3 = sspf(v3); }
            if (RESID) { v2 += resid[(size_t)r1*NN + nc]; v3 += resid[(size_t)r1*NN + nc + 1]; }
            Cout[(size_t)r1*NN + nc]     = v2;
            Cout[(size_t)r1*NN + nc + 1] = v3;
        }
    }
}

// -------- readout: pool h2 [N,64] per graph + atom counts --------
__global__ void pool2_kernel(const int* __restrict__ batch) {
    int idx = blockIdx.x * 256 + threadIdx.x;
    if (idx < N_ATOMS*64) {
        int n = idx >> 6, c = idx & 63;
        int b = batch[n];
        atomicAdd(&g_pool2[b*64 + c], g_h2[idx]);
        if (c == 0) atomicAdd(&g_cnt[b], 1.0f);
    }
}

// -------- final --------
__global__ void final_kernel(const float* __restrict__ out2w, const float* __restrict__ out2b,
                             const float* __restrict__ predw, const float* __restrict__ predb,
                             float* __restrict__ out)
{
    __shared__ float M[64*T_OUT];
    __shared__ float obp[T_OUT];
    int t = threadIdx.x;
    {
        int c = t >> 2, j = t & 3;
        float acc = 0.0f;
        for (int h = 0; h < H_DIM; h++)
            acc = fmaf(out2w[c*H_DIM + h], predw[h*T_OUT + j], acc);
        M[c*T_OUT + j] = acc;
    }
    if (t < T_OUT) {
        float acc = 0.0f;
        for (int h = 0; h < H_DIM; h++)
            acc = fmaf(out2b[h], predw[h*T_OUT + t], acc);
        obp[t] = acc;
    }
    __syncthreads();
    int b = t >> 2, j = t & 3;
    float acc = predb[j] + g_cnt[b] * obp[j];
    for (int c = 0; c < 64; c++)
        acc = fmaf(g_pool2[b*64 + c], M[c*T_OUT + j], acc);
    out[b*T_OUT + j] = acc;
}

extern "C" void kernel_launch(void* const* d_in, const int* in_sizes, int n_in,
                              void* d_out, int out_size)
{
    const int*   z      = (const int*)  d_in[0];
    const float* pos    = (const float*)d_in[1];
    const int*   batch  = (const int*)  d_in[2];
    const int*   ei     = (const int*)  d_in[3];
    const float* emb    = (const float*)d_in[4];
    const float* mlp_w1 = (const float*)d_in[5];
    const float* mlp_b1 = (const float*)d_in[6];
    const float* mlp_w2 = (const float*)d_in[7];
    const float* mlp_b2 = (const float*)d_in[8];
    const float* lin1_w = (const float*)d_in[9];
    const float* lin2_w = (const float*)d_in[10];
    const float* lin2_b = (const float*)d_in[11];
    const float* lin_w  = (const float*)d_in[12];
    const float* lin_b  = (const float*)d_in[13];
    const float* out1_w = (const float*)d_in[14];
    const float* out1_b = (const float*)d_in[15];
    const float* out2_w = (const float*)d_in[16];
    const float* out2_b = (const float*)d_in[17];
    const float* pred_w = (const float*)d_in[18];
    const float* pred_b = (const float*)d_in[19];
    float* out = (float*)d_out;

    void *h_p, *hx_p, *agg_p, *h2_p, *tbl_p, *pool_p, *cnt_p;
    cudaGetSymbolAddress(&h_p,    g_h);
    cudaGetSymbolAddress(&hx_p,   g_hx);
    cudaGetSymbolAddress(&agg_p,  g_agg);
    cudaGetSymbolAddress(&h2_p,   g_h2);
    cudaGetSymbolAddress(&tbl_p,  g_tbl);
    cudaGetSymbolAddress(&pool_p, g_pool2);
    cudaGetSymbolAddress(&cnt_p,  g_cnt);
    float* hF   = (float*)h_p;
    float* hxF  = (float*)hx_p;
    float* aggF = (float*)agg_p;
    float* h2F  = (float*)h2_p;
    float* tblF = (float*)tbl_p;

    const int smem128 = 128 * (128 + 8) * 4;   // 69632
    const int smem64  = 128 * (64 + 8) * 4;    // 36864
    cudaFuncSetAttribute(node_gemm_tc<128,false,false>, cudaFuncAttributeMaxDynamicSharedMemorySize, smem128);
    cudaFuncSetAttribute(node_gemm_tc<128,true ,false>, cudaFuncAttributeMaxDynamicSharedMemorySize, smem128);
    cudaFuncSetAttribute(node_gemm_tc<128,false,true >, cudaFuncAttributeMaxDynamicSharedMemorySize, smem128);
    cudaFuncSetAttribute(node_gemm_tc<64 ,true ,false>, cudaFuncAttributeMaxDynamicSharedMemorySize, smem64);

    embed_kernel<<<(N_ATOMS*H_DIM + 255)/256, 256>>>(z, emb);
    build_table<<<dim3(TBL, 2), H_DIM>>>(mlp_w1, mlp_b1, mlp_w2, mlp_b2);

    const int NB = (N_ATOMS + 127) / 128;
    const int EB = (E_EDGES / EPW + 7) / 8;
    for (int i = 0; i < 2; i++) {
        node_gemm_tc<128,false,false><<<NB,256,smem128>>>(hF, lin1_w + i*HH, nullptr, nullptr, hxF, N_ATOMS);
        cudaMemsetAsync(agg_p, 0, (size_t)N_ATOMS*H_DIM*sizeof(float));
        edge_pass<<<EB, 256>>>(ei, pos, tblF + i*TBL*H_DIM);
        node_gemm_tc<128,true ,false><<<NB,256,smem128>>>(aggF, lin2_w + i*HH, lin2_b + i*H_DIM, nullptr, hxF, N_ATOMS);
        node_gemm_tc<128,false,true ><<<NB,256,smem128>>>(hxF, lin_w + i*HH, lin_b + i*H_DIM, hF, hF, N_ATOMS);
    }

    node_gemm_tc<64,true,false><<<NB,256,smem64>>>(hF, out1_w, out1_b, nullptr, h2F, N_ATOMS);

    cudaMemsetAsync(pool_p, 0, (size_t)B_GR*64*sizeof(float));
    cudaMemsetAsync(cnt_p,  0, (size_t)B_GR*sizeof(float));
    pool2_kernel<<<(N_ATOMS*64 + 255)/256, 256>>>(batch);
    final_kernel<<<1, 256>>>(out2_w, out2_b, pred_w, pred_b, out);
}

// round 11
// speedup vs baseline: 7.7521x; 1.1517x over previous
#include <cuda_runtime.h>
#include <cuda_fp16.h>
#include <math.h>
#include <stdint.h>

#define N_ATOMS 50000
#define E_EDGES 1600000
#define H_DIM   128
#define B_GR    64
#define T_OUT   4
#define G_RBF   10
#define HH      (H_DIM*H_DIM)
#define TBL     1024
#define DMAX    10.0f

// -------- scratch (device globals; no allocations allowed) --------
__device__ float  g_h  [N_ATOMS*H_DIM];
__device__ float  g_hx [N_ATOMS*H_DIM];     // fp32 tmp (lin2 output)
__device__ __half g_hxh[N_ATOMS*H_DIM];     // half lin1 output (edge gather source)
__device__ float  g_agg[N_ATOMS*H_DIM];
__device__ float  g_h2 [N_ATOMS*64];
__device__ __half g_tblh[2*TBL*H_DIM];      // half filter tables W(d)
__device__ float  g_pool2[B_GR*64];
__device__ float  g_cnt[B_GR];

__device__ __forceinline__ float sspf(float x) {
    float sp = fmaxf(x, 0.0f) + log1pf(expf(-fabsf(x)));
    return sp - 0.69314718055994530942f;
}

__device__ __forceinline__ uint32_t tf32_of(float x) {
    uint32_t r;
    asm("cvt.rna.tf32.f32 %0, %1;" : "=r"(r) : "f"(x));
    return r;
}

__device__ __forceinline__ void mma_tf32(float* c, uint32_t a0, uint32_t a1,
                                         uint32_t a2, uint32_t a3,
                                         uint32_t b0, uint32_t b1) {
    asm volatile(
        "mma.sync.aligned.m16n8k8.row.col.f32.tf32.tf32.f32 "
        "{%0,%1,%2,%3}, {%4,%5,%6,%7}, {%8,%9}, {%0,%1,%2,%3};"
        : "+f"(c[0]), "+f"(c[1]), "+f"(c[2]), "+f"(c[3])
        : "r"(a0), "r"(a1), "r"(a2), "r"(a3), "r"(b0), "r"(b1));
}

// -------- filter table build (fp32 math, half store) --------
__global__ void build_table(const float* __restrict__ w1, const float* __restrict__ b1,
                            const float* __restrict__ w2, const float* __restrict__ b2)
{
    __shared__ float t1[H_DIM];
    const int k = blockIdx.x, it = blockIdx.y, h = threadIdx.x;
    const float d = (float)k * (DMAX / (float)(TBL - 1));
    const float step  = 10.0f / 9.0f;
    const float coeff = -0.405f;

    float v = b1[it*H_DIM + h];
    const float* w1p = w1 + it*G_RBF*H_DIM;
#pragma unroll
    for (int g = 0; g < G_RBF; g++) {
        float t = d - step * (float)g;
        v = fmaf(expf(coeff * t * t), w1p[g*H_DIM + h], v);
    }
    t1[h] = sspf(v);
    __syncthreads();

    const float* w2p = w2 + it*HH;
    float acc = b2[it*H_DIM + h];
#pragma unroll 8
    for (int kk = 0; kk < H_DIM; kk++)
        acc = fmaf(t1[kk], w2p[kk*H_DIM + h], acc);

    float C = 0.5f * (cospif(d * 0.1f) + 1.0f);
    g_tblh[(it*TBL + k)*H_DIM + h] = __float2half_rn(acc * C);
}

// -------- edge pass: one warp per edge, fp16 loads, fp32 math+red --------
#define EPW 2
__global__ void __launch_bounds__(256)
edge_pass(const int* __restrict__ ei, const float* __restrict__ pos,
          const __half* __restrict__ tbl)
{
    const int gw   = (blockIdx.x * 256 + threadIdx.x) >> 5;
    const int lane = threadIdx.x & 31;
    const int e0 = gw * EPW;
    const float scale = (float)(TBL - 1) / DMAX;

#pragma unroll
    for (int j = 0; j < EPW; j++) {
        int e = e0 + j;
        int s  = __ldg(&ei[e]);
        int dn = __ldg(&ei[E_EDGES + e]);
        float dx = __ldg(&pos[s*3+0]) - __ldg(&pos[dn*3+0]);
        float dy = __ldg(&pos[s*3+1]) - __ldg(&pos[dn*3+1]);
        float dz = __ldg(&pos[s*3+2]) - __ldg(&pos[dn*3+2]);
        float d = sqrtf(dx*dx + dy*dy + dz*dz);

        float tt = d * scale;
        int i0 = (int)tt;
        i0 = min(i0, TBL - 2);
        float f = tt - (float)i0;

        // 4 halves (8B) per lane from each table row; rows are 32 uint2 apart
        const uint2* ta = reinterpret_cast<const uint2*>(tbl + (size_t)i0 * H_DIM);
        uint2 av = __ldg(&ta[lane]);
        uint2 bv = __ldg(&ta[lane + 32]);
        uint2 xv = __ldg(reinterpret_cast<const uint2*>(g_hxh + (size_t)s * H_DIM) + lane);

        float2 a0 = __half22float2(*reinterpret_cast<__half2*>(&av.x));
        float2 a1 = __half22float2(*reinterpret_cast<__half2*>(&av.y));
        float2 b0 = __half22float2(*reinterpret_cast<__half2*>(&bv.x));
        float2 b1 = __half22float2(*reinterpret_cast<__half2*>(&bv.y));
        float2 x0 = __half22float2(*reinterpret_cast<__half2*>(&xv.x));
        float2 x1 = __half22float2(*reinterpret_cast<__half2*>(&xv.y));

        float w0 = fmaf(f, b0.x - a0.x, a0.x) * x0.x;
        float w1 = fmaf(f, b0.y - a0.y, a0.y) * x0.y;
        float w2 = fmaf(f, b1.x - a1.x, a1.x) * x1.x;
        float w3 = fmaf(f, b1.y - a1.y, a1.y) * x1.y;

        float* ap = g_agg + (size_t)dn*H_DIM + lane*4;
        asm volatile("red.global.add.v4.f32 [%0], {%1,%2,%3,%4};"
                     :: "l"(ap), "f"(w0), "f"(w1), "f"(w2), "f"(w3) : "memory");
    }
}

// -------- tensor-core node GEMM (tf32 HMMA) --------
// C[M,NN] = op(A[gidxA?][128] @ W[128,NN] + bias) (+resid[gidxR?])
// OUTH: write half output (for edge gather source)
template<int NN, bool SSP_, bool RESID, bool OUTH>
__global__ void __launch_bounds__(256)
node_gemm_tc(const float* __restrict__ A, const int* __restrict__ gidxA,
             const float* __restrict__ W, const float* __restrict__ bias,
             const float* __restrict__ resid, const int* __restrict__ gidxR,
             void* __restrict__ CoutV, int M)
{
    constexpr int S  = NN + 8;
    constexpr int NT = NN / 8;
    extern __shared__ float sW[];   // [128][S]

    const int tid = threadIdx.x;
    for (int idx = tid; idx < 128*NN; idx += 256) {
        int k = idx / NN, n = idx - k*NN;
        sW[k*S + n] = __uint_as_float(tf32_of(W[idx]));
    }
    __syncthreads();

    const int warp = tid >> 5, lane = tid & 31;
    const int row0 = blockIdx.x * 128 + warp * 16;
    const int g  = lane >> 2;
    const int qc = lane & 3;
    int rA0 = min(row0 + g,     M - 1);
    int rA1 = min(row0 + 8 + g, M - 1);
    if (gidxA) { rA0 = gidxA[rA0]; rA1 = gidxA[rA1]; }
    const float* A0 = A + (size_t)rA0 * 128 + qc;
    const float* A1 = A + (size_t)rA1 * 128 + qc;

    float acc[NT][4];
#pragma unroll
    for (int t = 0; t < NT; t++)
#pragma unroll
        for (int i = 0; i < 4; i++) acc[t][i] = 0.0f;

#pragma unroll
    for (int k0 = 0; k0 < 128; k0 += 8) {
        uint32_t a0 = tf32_of(__ldg(A0 + k0));
        uint32_t a2 = tf32_of(__ldg(A0 + k0 + 4));
        uint32_t a1 = tf32_of(__ldg(A1 + k0));
        uint32_t a3 = tf32_of(__ldg(A1 + k0 + 4));
        const float* bp0 = sW + (k0 + qc) * S + g;
        const float* bp1 = bp0 + 4 * S;
#pragma unroll
        for (int t = 0; t < NT; t++) {
            uint32_t b0 = __float_as_uint(bp0[t*8]);
            uint32_t b1 = __float_as_uint(bp1[t*8]);
            mma_tf32(acc[t], a0, a1, a2, a3, b0, b1);
        }
    }

    const int r0 = row0 + g;
    const int r1 = r0 + 8;
    int rR0 = 0, rR1 = 0;
    if (RESID) {
        rR0 = min(r0, M - 1); rR1 = min(r1, M - 1);
        if (gidxR) { rR0 = gidxR[rR0]; rR1 = gidxR[rR1]; }
    }
#pragma unroll
    for (int t = 0; t < NT; t++) {
        int nc = t*8 + 2*qc;
        float bias0 = 0.f, bias1 = 0.f;
        if (bias) { bias0 = bias[nc]; bias1 = bias[nc+1]; }
        if (r0 < M) {
            float v0 = acc[t][0] + bias0;
            float v1 = acc[t][1] + bias1;
            if (SSP_) { v0 = sspf(v0); v1 = sspf(v1); }
            if (RESID) { v0 += resid[(size_t)rR0*NN + nc]; v1 += resid[(size_t)rR0*NN + nc + 1]; }
            if (OUTH) {
                *reinterpret_cast<__half2*>((__half*)CoutV + (size_t)r0*NN + nc) =
                    __floats2half2_rn(v0, v1);
            } else {
                float* Cout = (float*)CoutV;
                Cout[(size_t)r0*NN + nc]     = v0;
                Cout[(size_t)r0*NN + nc + 1] = v1;
            }
        }
        if (r1 < M) {
            float v2 = acc[t][2] + bias0;
            float v3 = acc[t][3] + bias1;
            if (SSP_) { v2 = sspf(v2); v3 = sspf(v3); }
            if (RESID) { v2 += resid[(size_t)rR1*NN + nc]; v3 += resid[(size_t)rR1*NN + nc + 1]; }
            if (OUTH) {
                *reinterpret_cast<__half2*>((__half*)CoutV + (size_t)r1*NN + nc) =
                    __floats2half2_rn(v2, v3);
            } else {
                float* Cout = (float*)CoutV;
                Cout[(size_t)r1*NN + nc]     = v2;
                Cout[(size_t)r1*NN + nc + 1] = v3;
            }
        }
    }
}

// -------- readout: pool h2 [N,64] per graph + atom counts --------
__global__ void pool2_kernel(const int* __restrict__ batch) {
    int idx = blockIdx.x * 256 + threadIdx.x;
    if (idx < N_ATOMS*64) {
        int n = idx >> 6, c = idx & 63;
        int b = batch[n];
        atomicAdd(&g_pool2[b*64 + c], g_h2[idx]);
        if (c == 0) atomicAdd(&g_cnt[b], 1.0f);
    }
}

// -------- final --------
__global__ void final_kernel(const float* __restrict__ out2w, const float* __restrict__ out2b,
                             const float* __restrict__ predw, const float* __restrict__ predb,
                             float* __restrict__ out)
{
    __shared__ float M[64*T_OUT];
    __shared__ float obp[T_OUT];
    int t = threadIdx.x;
    {
        int c = t >> 2, j = t & 3;
        float acc = 0.0f;
        for (int h = 0; h < H_DIM; h++)
            acc = fmaf(out2w[c*H_DIM + h], predw[h*T_OUT + j], acc);
        M[c*T_OUT + j] = acc;
    }
    if (t < T_OUT) {
        float acc = 0.0f;
        for (int h = 0; h < H_DIM; h++)
            acc = fmaf(out2b[h], predw[h*T_OUT + t], acc);
        obp[t] = acc;
    }
    __syncthreads();
    int b = t >> 2, j = t & 3;
    float acc = predb[j] + g_cnt[b] * obp[j];
    for (int c = 0; c < 64; c++)
        acc = fmaf(g_pool2[b*64 + c], M[c*T_OUT + j], acc);
    out[b*T_OUT + j] = acc;
}

extern "C" void kernel_launch(void* const* d_in, const int* in_sizes, int n_in,
                              void* d_out, int out_size)
{
    const int*   z      = (const int*)  d_in[0];
    const float* pos    = (const float*)d_in[1];
    const int*   batch  = (const int*)  d_in[2];
    const int*   ei     = (const int*)  d_in[3];
    const float* emb    = (const float*)d_in[4];
    const float* mlp_w1 = (const float*)d_in[5];
    const float* mlp_b1 = (const float*)d_in[6];
    const float* mlp_w2 = (const float*)d_in[7];
    const float* mlp_b2 = (const float*)d_in[8];
    const float* lin1_w = (const float*)d_in[9];
    const float* lin2_w = (const float*)d_in[10];
    const float* lin2_b = (const float*)d_in[11];
    const float* lin_w  = (const float*)d_in[12];
    const float* lin_b  = (const float*)d_in[13];
    const float* out1_w = (const float*)d_in[14];
    const float* out1_b = (const float*)d_in[15];
    const float* out2_w = (const float*)d_in[16];
    const float* out2_b = (const float*)d_in[17];
    const float* pred_w = (const float*)d_in[18];
    const float* pred_b = (const float*)d_in[19];
    float* out = (float*)d_out;

    void *h_p, *hx_p, *hxh_p, *agg_p, *h2_p, *tbl_p, *pool_p, *cnt_p;
    cudaGetSymbolAddress(&h_p,    g_h);
    cudaGetSymbolAddress(&hx_p,   g_hx);
    cudaGetSymbolAddress(&hxh_p,  g_hxh);
    cudaGetSymbolAddress(&agg_p,  g_agg);
    cudaGetSymbolAddress(&h2_p,   g_h2);
    cudaGetSymbolAddress(&tbl_p,  g_tblh);
    cudaGetSymbolAddress(&pool_p, g_pool2);
    cudaGetSymbolAddress(&cnt_p,  g_cnt);
    float*  hF   = (float*)h_p;
    float*  hxF  = (float*)hx_p;
    float*  aggF = (float*)agg_p;
    float*  h2F  = (float*)h2_p;
    __half* tblH = (__half*)tbl_p;

    const int smem128 = 128 * (128 + 8) * 4;
    const int smem64  = 128 * (64 + 8) * 4;
    cudaFuncSetAttribute(node_gemm_tc<128,false,false,true >, cudaFuncAttributeMaxDynamicSharedMemorySize, smem128);
    cudaFuncSetAttribute(node_gemm_tc<128,true ,false,false>, cudaFuncAttributeMaxDynamicSharedMemorySize, smem128);
    cudaFuncSetAttribute(node_gemm_tc<128,false,true ,false>, cudaFuncAttributeMaxDynamicSharedMemorySize, smem128);
    cudaFuncSetAttribute(node_gemm_tc<64 ,true ,false,false>, cudaFuncAttributeMaxDynamicSharedMemorySize, smem64);

    build_table<<<dim3(TBL, 2), H_DIM>>>(mlp_w1, mlp_b1, mlp_w2, mlp_b2);

    const int NB = (N_ATOMS + 127) / 128;
    const int EB = E_EDGES / (EPW * 8);   // exact: 100000 blocks
    for (int i = 0; i < 2; i++) {
        // hxh = (A @ lin1_w) in half; A = emb gathered by z for i=0, else h
        if (i == 0)
            node_gemm_tc<128,false,false,true ><<<NB,256,smem128>>>(emb, z, lin1_w, nullptr, nullptr, nullptr, hxh_p, N_ATOMS);
        else
            node_gemm_tc<128,false,false,true ><<<NB,256,smem128>>>(hF, nullptr, lin1_w + HH, nullptr, nullptr, nullptr, hxh_p, N_ATOMS);
        cudaMemsetAsync(agg_p, 0, (size_t)N_ATOMS*H_DIM*sizeof(float));
        edge_pass<<<EB, 256>>>(ei, pos, tblH + i*TBL*H_DIM);
        // tmp = ssp(agg @ lin2_w + lin2_b)
        node_gemm_tc<128,true ,false,false><<<NB,256,smem128>>>(aggF, nullptr, lin2_w + i*HH, lin2_b + i*H_DIM, nullptr, nullptr, hxF, N_ATOMS);
        // h = resid + (tmp @ lin_w + lin_b); resid = emb[z] for i=0, else h
        if (i == 0)
            node_gemm_tc<128,false,true ,false><<<NB,256,smem128>>>(hxF, nullptr, lin_w, lin_b, emb, z, hF, N_ATOMS);
        else
            node_gemm_tc<128,false,true ,false><<<NB,256,smem128>>>(hxF, nullptr, lin_w + HH, lin_b + H_DIM, hF, nullptr, hF, N_ATOMS);
    }

    node_gemm_tc<64,true,false,false><<<NB,256,smem64>>>(hF, nullptr, out1_w, out1_b, nullptr, nullptr, h2F, N_ATOMS);

    cudaMemsetAsync(pool_p, 0, (size_t)B_GR*64*sizeof(float));
    cudaMemsetAsync(cnt_p,  0, (size_t)B_GR*sizeof(float));
    pool2_kernel<<<(N_ATOMS*64 + 255)/256, 256>>>(batch);
    final_kernel<<<1, 256>>>(out2_w, out2_b, pred_w, pred_b, out);
}